// round 1
// baseline (speedup 1.0000x reference)
#include <cuda_runtime.h>
#include <math.h>

#define TPB 256          // threads per block
#define MPT 64           // points per block
#define AS  68           // activation row stride in floats (68*4=272B, 16B aligned, 4-way-max store conflicts)
#define KC  16           // k-chunk for weight staging

typedef unsigned long long u64;

struct NerfParams {
    const float* pts;
    const float* dirs;
    const float* Wb[8];
    const float* bb[8];
    const float* Wsig; const float* bsig;
    const float* Wrm;  const float* brm;
    const float* Wr0;  const float* br0;
    const float* Wr1;  const float* br1;
    float* out;
    int N;
};

__device__ __forceinline__ void fma2(u64 &acc, u64 a, u64 b){
    asm("fma.rn.f32x2 %0, %1, %2, %0;" : "+l"(acc) : "l"(a), "l"(b));
}
__device__ __forceinline__ u64 pack2(float w){
    u64 r; asm("mov.b64 %0, {%1, %1};" : "=l"(r) : "f"(w)); return r;
}
__device__ __forceinline__ void unpack2(u64 a, float &lo, float &hi){
    asm("mov.b64 {%0, %1}, %2;" : "=f"(lo), "=f"(hi) : "l"(a));
}

// Accumulate acc[m-pairs] += buf[k][m] * Wg[j][k] for k in [kbeg, kend).
// buf row 0 corresponds to k = kbeg (k-major SMEM, stride AS floats).
// Thread tid owns output neuron j = tid (tid < NOUT).
template<int NOUT>
__device__ __forceinline__ void gemm_pass(u64 acc[32],
        const float* __restrict__ Wg, int wstride,
        int kbeg, int kend, const float* buf, float* Ws, int tid)
{
    #pragma unroll 1
    for (int k0 = kbeg; k0 < kend; k0 += KC){
        int kc = min(KC, kend - k0);
        __syncthreads();
        // stage weight chunk Ws[j][kk], j < NOUT (coalesced from L2)
        #pragma unroll 1
        for (int idx = tid; idx < NOUT*KC; idx += TPB){
            int j = idx >> 4, kk = idx & 15;
            float w = (kk < kc) ? Wg[j*wstride + k0 + kk] : 0.0f;
            Ws[j*17 + kk] = w;
        }
        __syncthreads();
        if (tid < NOUT){
            const float* rowp = buf + (k0 - kbeg)*AS;
            #pragma unroll 1
            for (int kk = 0; kk < kc; kk++){
                u64 w2 = pack2(Ws[tid*17 + kk]);       // conflict-free (17 odd)
                const ulonglong2* row = (const ulonglong2*)rowp;  // broadcast LDS.128
                #pragma unroll
                for (int i = 0; i < 16; i++){
                    ulonglong2 v = row[i];
                    fma2(acc[2*i+0], v.x, w2);
                    fma2(acc[2*i+1], v.y, w2);
                }
                rowp += AS;
            }
        }
    }
}

template<int NOUT>
__device__ __forceinline__ void writeback_relu(u64 acc[32], const float* __restrict__ bg,
                                               float* dst0, int tid)
{
    __syncthreads();   // all reads of the input buffer must be done before overwrite
    if (tid < NOUT){
        float b = bg[tid];
        float* dst = dst0 + tid*AS;
        #pragma unroll
        for (int i = 0; i < 32; i++){
            float lo, hi; unpack2(acc[i], lo, hi);
            dst[2*i+0] = fmaxf(lo + b, 0.0f);
            dst[2*i+1] = fmaxf(hi + b, 0.0f);
        }
    }
}

__device__ __forceinline__ void zero_acc(u64 acc[32]){
    #pragma unroll
    for (int i = 0; i < 32; i++) acc[i] = 0ull;
}

__global__ void __launch_bounds__(TPB, 2) nerf_fused(NerfParams P)
{
    extern __shared__ float sm[];
    float* A  = sm;                 // [256][AS] activations (k-major)
    float* Pe = A  + 256*AS;        // [63][AS]  embedded pts
    float* De = Pe + 63*AS;         // [27][AS]  embedded dirs
    float* Ws = De + 27*AS;         // [256][17] weight staging
    const int tid = threadIdx.x;
    const int g0  = blockIdx.x * MPT;
    const int N   = P.N;

    // ---- embeddings: [x, sin(2^f x), cos(2^f x), ...] per dim, f ascending ----
    for (int idx = tid; idx < MPT*3; idx += TPB){
        int m = idx/3, d = idx%3;
        Pe[d*AS+m] = P.pts [(g0+m)*3+d];
        De[d*AS+m] = P.dirs[(g0+m)*3+d];
    }
    for (int idx = tid; idx < MPT*30; idx += TPB){
        int m = idx/30, q = idx%30, f = q/3, d = q%3;
        float x = P.pts[(g0+m)*3+d] * (float)(1<<f);
        float s, c; sincosf(x, &s, &c);
        Pe[(3+f*6+d)*AS+m]   = s;
        Pe[(3+f*6+3+d)*AS+m] = c;
    }
    for (int idx = tid; idx < MPT*12; idx += TPB){
        int m = idx/12, q = idx%12, f = q/3, d = q%3;
        float x = P.dirs[(g0+m)*3+d] * (float)(1<<f);
        float s, c; sincosf(x, &s, &c);
        De[(3+f*6+d)*AS+m]   = s;
        De[(3+f*6+3+d)*AS+m] = c;
    }
    __syncthreads();

    // ---- third output: embedded dirs, out[4N + n*27 + k] ----
    {
        float* outD = P.out + 4ll*N;
        for (int idx = tid; idx < MPT*27; idx += TPB){
            int m = idx/27, k = idx%27;
            outD[(long long)(g0+m)*27 + k] = De[k*AS+m];
        }
    }

    u64 acc[32];

    // ---- layer 0: 63 -> 256 ----
    zero_acc(acc);
    gemm_pass<256>(acc, P.Wb[0], 63, 0, 63, Pe, Ws, tid);
    writeback_relu<256>(acc, P.bb[0], A, tid);

    // ---- layers 1..4: 256 -> 256 ----
    #pragma unroll 1
    for (int L = 1; L <= 4; L++){
        zero_acc(acc);
        gemm_pass<256>(acc, P.Wb[L], 256, 0, 256, A, Ws, tid);
        writeback_relu<256>(acc, P.bb[L], A, tid);
    }

    // ---- layer 5 with skip: [p(63), base(256)] -> 256 ----
    zero_acc(acc);
    gemm_pass<256>(acc, P.Wb[5], 319, 0, 63, Pe, Ws, tid);
    gemm_pass<256>(acc, P.Wb[5], 319, 63, 319, A, Ws, tid);
    writeback_relu<256>(acc, P.bb[5], A, tid);

    // ---- layers 6, 7: 256 -> 256 ----
    #pragma unroll 1
    for (int L = 6; L <= 7; L++){
        zero_acc(acc);
        gemm_pass<256>(acc, P.Wb[L], 256, 0, 256, A, Ws, tid);
        writeback_relu<256>(acc, P.bb[L], A, tid);
    }

    // ---- sigma = base @ Wsig.T + bsig  (SIGMA_MUL=0 -> identity afterwards) ----
    __syncthreads();
    Ws[tid] = P.Wsig[tid];          // stage the 256-vector
    __syncthreads();
    if (tid < MPT){
        float s = P.bsig[0];
        #pragma unroll 8
        for (int k = 0; k < 256; k++) s += A[k*AS+tid] * Ws[k];
        P.out[3ll*N + g0 + tid] = s;
    }
    // (remap's first __syncthreads orders Ws reuse after these reads)

    // ---- base_remap = relu(base @ Wrm.T + brm) ----
    zero_acc(acc);
    gemm_pass<256>(acc, P.Wrm, 256, 0, 256, A, Ws, tid);
    writeback_relu<256>(acc, P.brm, A, tid);

    // ---- rgb_fea = relu([remap(256), d(27)] @ Wr0.T + br0), 128 outputs ----
    zero_acc(acc);
    gemm_pass<128>(acc, P.Wr0, 283, 0, 256, A, Ws, tid);
    gemm_pass<128>(acc, P.Wr0, 283, 256, 283, De, Ws, tid);
    writeback_relu<128>(acc, P.br0, A, tid);   // overwrites A rows 0..127
    __syncthreads();

    // ---- rgb = sigmoid(fea @ Wr1.T + br1) ----
    for (int idx = tid; idx < 384; idx += TPB) Ws[idx] = P.Wr1[idx];
    __syncthreads();
    if (tid < MPT){
        #pragma unroll
        for (int c = 0; c < 3; c++){
            float a = P.br1[c];
            #pragma unroll 8
            for (int k = 0; k < 128; k++) a += A[k*AS+tid] * Ws[c*128+k];
            P.out[(long long)(g0+tid)*3 + c] = 1.0f/(1.0f + expf(-a));
        }
    }
}

extern "C" void kernel_launch(void* const* d_in, const int* in_sizes, int n_in,
                              void* d_out, int out_size)
{
    NerfParams p;
    p.pts  = (const float*)d_in[0];
    p.dirs = (const float*)d_in[1];
    for (int i = 0; i < 8; i++){
        p.Wb[i] = (const float*)d_in[2 + 2*i];
        p.bb[i] = (const float*)d_in[3 + 2*i];
    }
    p.Wsig = (const float*)d_in[18]; p.bsig = (const float*)d_in[19];
    p.Wrm  = (const float*)d_in[20]; p.brm  = (const float*)d_in[21];
    p.Wr0  = (const float*)d_in[22]; p.br0  = (const float*)d_in[23];
    p.Wr1  = (const float*)d_in[24]; p.br1  = (const float*)d_in[25];
    p.out  = (float*)d_out;
    p.N    = in_sizes[0] / 3;

    size_t smem = (size_t)(256*AS + 63*AS + 27*AS + 256*17) * sizeof(float); // 111,520 B
    cudaFuncSetAttribute(nerf_fused, cudaFuncAttributeMaxDynamicSharedMemorySize, (int)smem);

    int blocks = p.N / MPT;   // N = 262144 -> 4096
    nerf_fused<<<blocks, TPB, smem>>>(p);
}

// round 2
// speedup vs baseline: 1.1023x; 1.1023x over previous
#include <cuda_runtime.h>
#include <math.h>

#define TPB 256          // threads per block
#define MPT 64           // points per block
#define AS  68           // activation row stride in floats (272B, 16B aligned)
#define KC  16           // k-chunk for weight staging
#define WSS 260          // Ws row stride (floats), 16B aligned

typedef unsigned long long u64;

struct NerfParams {
    const float* pts;
    const float* dirs;
    const float* Wb[8];
    const float* bb[8];
    const float* Wsig; const float* bsig;
    const float* Wrm;  const float* brm;
    const float* Wr0;  const float* br0;
    const float* Wr1;  const float* br1;
    float* out;
    int N;
};

__device__ __forceinline__ void fma2(u64 &acc, u64 a, u64 b){
    asm("fma.rn.f32x2 %0, %1, %2, %0;" : "+l"(acc) : "l"(a), "l"(b));
}
__device__ __forceinline__ u64 pack2(float w){
    u64 r; asm("mov.b64 %0, {%1, %1};" : "=l"(r) : "f"(w)); return r;
}
__device__ __forceinline__ void unpack2(u64 a, float &lo, float &hi){
    asm("mov.b64 {%0, %1}, %2;" : "=f"(lo), "=f"(hi) : "l"(a));
}

// acc layout: acc[jj*8 + i*2 + p] is an f32x2 pair covering points
//   m = i*16 + mq*4 + 2p + {0,1},  for output j = jq*4 + jj.
// buf is k-major SMEM (row stride AS); buf row 0 is k = kbeg.
template<int NOUT>
__device__ __forceinline__ void gemm_pass(u64 acc[32],
        const float* __restrict__ Wg, int wstride,
        int kbeg, int kend, const float* buf, float* Ws,
        int tid, int jq, int mq)
{
    #pragma unroll 1
    for (int k0 = kbeg; k0 < kend; k0 += KC){
        int kc = min(KC, kend - k0);
        __syncthreads();
        // stage weights: Ws[kk][j] = Wg[j][k0+kk]  (global coalesced over kk)
        #pragma unroll 1
        for (int idx = tid; idx < NOUT*KC; idx += TPB){
            int j = idx >> 4, kk = idx & 15;
            if (kk < kc) Ws[kk*WSS + j] = Wg[j*wstride + k0 + kk];
        }
        __syncthreads();
        if (jq*4 < NOUT){
            const float* rowp = buf + (k0 - kbeg)*AS + mq*4;
            const float* wsp  = Ws + jq*4;
            #pragma unroll 1
            for (int kk = 0; kk < kc; kk++){
                float4 wv = *(const float4*)(wsp + kk*WSS);   // 4 weights, 1 LDS.128
                u64 w0 = pack2(wv.x), w1 = pack2(wv.y), w2v = pack2(wv.z), w3 = pack2(wv.w);
                ulonglong2 a0 = *(const ulonglong2*)(rowp);      // m: mq*4 + 0..3
                ulonglong2 a1 = *(const ulonglong2*)(rowp + 16); // m: 16 + mq*4 ..
                ulonglong2 a2 = *(const ulonglong2*)(rowp + 32);
                ulonglong2 a3 = *(const ulonglong2*)(rowp + 48);
                fma2(acc[ 0], a0.x, w0); fma2(acc[ 1], a0.y, w0);
                fma2(acc[ 2], a1.x, w0); fma2(acc[ 3], a1.y, w0);
                fma2(acc[ 4], a2.x, w0); fma2(acc[ 5], a2.y, w0);
                fma2(acc[ 6], a3.x, w0); fma2(acc[ 7], a3.y, w0);
                fma2(acc[ 8], a0.x, w1); fma2(acc[ 9], a0.y, w1);
                fma2(acc[10], a1.x, w1); fma2(acc[11], a1.y, w1);
                fma2(acc[12], a2.x, w1); fma2(acc[13], a2.y, w1);
                fma2(acc[14], a3.x, w1); fma2(acc[15], a3.y, w1);
                fma2(acc[16], a0.x, w2v); fma2(acc[17], a0.y, w2v);
                fma2(acc[18], a1.x, w2v); fma2(acc[19], a1.y, w2v);
                fma2(acc[20], a2.x, w2v); fma2(acc[21], a2.y, w2v);
                fma2(acc[22], a3.x, w2v); fma2(acc[23], a3.y, w2v);
                fma2(acc[24], a0.x, w3); fma2(acc[25], a0.y, w3);
                fma2(acc[26], a1.x, w3); fma2(acc[27], a1.y, w3);
                fma2(acc[28], a2.x, w3); fma2(acc[29], a2.y, w3);
                fma2(acc[30], a3.x, w3); fma2(acc[31], a3.y, w3);
                rowp += AS;
            }
        }
    }
}

template<int NOUT>
__device__ __forceinline__ void writeback_relu(u64 acc[32], const float* __restrict__ bg,
                                               float* dst0, int tid, int jq, int mq)
{
    __syncthreads();   // all reads of the input buffer done before overwrite
    if (jq*4 < NOUT){
        #pragma unroll
        for (int jj = 0; jj < 4; jj++){
            int j = jq*4 + jj;
            float b = bg[j];
            float* dst = dst0 + j*AS + mq*4;
            #pragma unroll
            for (int i = 0; i < 4; i++){
                #pragma unroll
                for (int p = 0; p < 2; p++){
                    float lo, hi; unpack2(acc[jj*8 + i*2 + p], lo, hi);
                    float2 v = make_float2(fmaxf(lo + b, 0.0f), fmaxf(hi + b, 0.0f));
                    *(float2*)(dst + i*16 + 2*p) = v;
                }
            }
        }
    }
}

__device__ __forceinline__ void zero_acc(u64 acc[32]){
    #pragma unroll
    for (int i = 0; i < 32; i++) acc[i] = 0ull;
}

__global__ void __launch_bounds__(TPB, 2) nerf_fused(NerfParams P)
{
    extern __shared__ float sm[];
    float* A  = sm;                 // [256][AS] activations (k-major)
    float* Pe = A  + 256*AS;        // [63][AS]  embedded pts
    float* De = Pe + 63*AS;         // [27][AS]  embedded dirs
    float* Ws = De + 27*AS;         // weight staging: [KC][WSS]
    const int tid = threadIdx.x;
    const int jq  = tid >> 2;       // 0..63  (4 outputs each)
    const int mq  = tid & 3;        // 0..3   (16 points each, interleaved by 4)
    const int g0  = blockIdx.x * MPT;
    const int N   = P.N;

    // ---- embeddings: [x, sin(2^f x)*3, cos(2^f x)*3, ...] f ascending ----
    for (int idx = tid; idx < MPT*3; idx += TPB){
        int m = idx/3, d = idx%3;
        Pe[d*AS+m] = P.pts [(g0+m)*3+d];
        De[d*AS+m] = P.dirs[(g0+m)*3+d];
    }
    for (int idx = tid; idx < MPT*30; idx += TPB){
        int m = idx/30, q = idx%30, f = q/3, d = q%3;
        float x = P.pts[(g0+m)*3+d] * (float)(1<<f);
        float s, c; sincosf(x, &s, &c);
        Pe[(3+f*6+d)*AS+m]   = s;
        Pe[(3+f*6+3+d)*AS+m] = c;
    }
    for (int idx = tid; idx < MPT*12; idx += TPB){
        int m = idx/12, q = idx%12, f = q/3, d = q%3;
        float x = P.dirs[(g0+m)*3+d] * (float)(1<<f);
        float s, c; sincosf(x, &s, &c);
        De[(3+f*6+d)*AS+m]   = s;
        De[(3+f*6+3+d)*AS+m] = c;
    }
    __syncthreads();

    // ---- third output: embedded dirs, out[4N + n*27 + k] ----
    {
        float* outD = P.out + 4ll*N;
        for (int idx = tid; idx < MPT*27; idx += TPB){
            int m = idx/27, k = idx%27;
            outD[(long long)(g0+m)*27 + k] = De[k*AS+m];
        }
    }

    u64 acc[32];

    // ---- layer 0: 63 -> 256 ----
    zero_acc(acc);
    gemm_pass<256>(acc, P.Wb[0], 63, 0, 63, Pe, Ws, tid, jq, mq);
    writeback_relu<256>(acc, P.bb[0], A, tid, jq, mq);

    // ---- layers 1..4: 256 -> 256 ----
    #pragma unroll 1
    for (int L = 1; L <= 4; L++){
        zero_acc(acc);
        gemm_pass<256>(acc, P.Wb[L], 256, 0, 256, A, Ws, tid, jq, mq);
        writeback_relu<256>(acc, P.bb[L], A, tid, jq, mq);
    }

    // ---- layer 5 with skip: [p(63), base(256)] -> 256 ----
    zero_acc(acc);
    gemm_pass<256>(acc, P.Wb[5], 319, 0, 63, Pe, Ws, tid, jq, mq);
    gemm_pass<256>(acc, P.Wb[5], 319, 63, 319, A, Ws, tid, jq, mq);
    writeback_relu<256>(acc, P.bb[5], A, tid, jq, mq);

    // ---- layers 6, 7: 256 -> 256 ----
    #pragma unroll 1
    for (int L = 6; L <= 7; L++){
        zero_acc(acc);
        gemm_pass<256>(acc, P.Wb[L], 256, 0, 256, A, Ws, tid, jq, mq);
        writeback_relu<256>(acc, P.bb[L], A, tid, jq, mq);
    }

    // ---- sigma = base @ Wsig.T + bsig (SIGMA_MUL=0) ----
    __syncthreads();
    Ws[tid] = P.Wsig[tid];          // stage the 256-vector
    __syncthreads();
    if (tid < MPT){
        float s = P.bsig[0];
        #pragma unroll 8
        for (int k = 0; k < 256; k++) s += A[k*AS+tid] * Ws[k];
        P.out[3ll*N + g0 + tid] = s;
    }
    // (next gemm_pass's first __syncthreads orders Ws reuse after these reads)

    // ---- base_remap = relu(base @ Wrm.T + brm) ----
    zero_acc(acc);
    gemm_pass<256>(acc, P.Wrm, 256, 0, 256, A, Ws, tid, jq, mq);
    writeback_relu<256>(acc, P.brm, A, tid, jq, mq);

    // ---- rgb_fea = relu([remap(256), d(27)] @ Wr0.T + br0), 128 outputs ----
    zero_acc(acc);
    gemm_pass<128>(acc, P.Wr0, 283, 0, 256, A, Ws, tid, jq, mq);
    gemm_pass<128>(acc, P.Wr0, 283, 256, 283, De, Ws, tid, jq, mq);
    writeback_relu<128>(acc, P.br0, A, tid, jq, mq);   // overwrites A rows 0..127
    __syncthreads();

    // ---- rgb = sigmoid(fea @ Wr1.T + br1) ----
    for (int idx = tid; idx < 384; idx += TPB) Ws[idx] = P.Wr1[idx];
    __syncthreads();
    if (tid < MPT){
        #pragma unroll
        for (int c = 0; c < 3; c++){
            float a = P.br1[c];
            #pragma unroll 8
            for (int k = 0; k < 128; k++) a += A[k*AS+tid] * Ws[c*128+k];
            P.out[(long long)(g0+tid)*3 + c] = 1.0f/(1.0f + expf(-a));
        }
    }
}

extern "C" void kernel_launch(void* const* d_in, const int* in_sizes, int n_in,
                              void* d_out, int out_size)
{
    NerfParams p;
    p.pts  = (const float*)d_in[0];
    p.dirs = (const float*)d_in[1];
    for (int i = 0; i < 8; i++){
        p.Wb[i] = (const float*)d_in[2 + 2*i];
        p.bb[i] = (const float*)d_in[3 + 2*i];
    }
    p.Wsig = (const float*)d_in[18]; p.bsig = (const float*)d_in[19];
    p.Wrm  = (const float*)d_in[20]; p.brm  = (const float*)d_in[21];
    p.Wr0  = (const float*)d_in[22]; p.br0  = (const float*)d_in[23];
    p.Wr1  = (const float*)d_in[24]; p.br1  = (const float*)d_in[25];
    p.out  = (float*)d_out;
    p.N    = in_sizes[0] / 3;

    size_t smem = (size_t)(256*AS + 63*AS + 27*AS + KC*WSS + 192) * sizeof(float);
    cudaFuncSetAttribute(nerf_fused, cudaFuncAttributeMaxDynamicSharedMemorySize, (int)smem);

    int blocks = p.N / MPT;   // 262144/64 = 4096
    nerf_fused<<<blocks, TPB, smem>>>(p);
}

// round 3
// speedup vs baseline: 1.1032x; 1.0008x over previous
#include <cuda_runtime.h>
#include <math.h>

#define TPB 256          // threads per block
#define MPT 64           // points per block
#define AS  68           // activation row stride in floats (272B, 16B aligned)
#define KC  16           // k-chunk for weight staging
#define WSS 260          // Ws row stride (floats), 16B aligned

typedef unsigned long long u64;

struct NerfParams {
    const float* pts;
    const float* dirs;
    const float* Wb[8];
    const float* bb[8];
    const float* Wsig; const float* bsig;
    const float* Wrm;  const float* brm;
    const float* Wr0;  const float* br0;
    const float* Wr1;  const float* br1;
    float* out;
    int N;
};

__device__ __forceinline__ void fma2(u64 &acc, u64 a, u64 b){
    asm("fma.rn.f32x2 %0, %1, %2, %0;" : "+l"(acc) : "l"(a), "l"(b));
}
__device__ __forceinline__ u64 pack2(float w){
    u64 r; asm("mov.b64 %0, {%1, %1};" : "=l"(r) : "f"(w)); return r;
}
__device__ __forceinline__ void unpack2(u64 a, float &lo, float &hi){
    asm("mov.b64 {%0, %1}, %2;" : "=f"(lo), "=f"(hi) : "l"(a));
}

// acc layout: acc[jj*8 + i*2 + p] is an f32x2 pair covering points
//   m = i*16 + mq*4 + 2p + {0,1},  for output j = jq*4 + jj.
// buf is k-major SMEM (row stride AS); buf row 0 is k = kbeg.
template<int NOUT>
__device__ __forceinline__ void gemm_pass(u64 acc[32],
        const float* __restrict__ Wg, int wstride,
        int kbeg, int kend, const float* buf, float* Ws,
        int tid, int jq, int mq)
{
    #pragma unroll 1
    for (int k0 = kbeg; k0 < kend; k0 += KC){
        int kc = min(KC, kend - k0);
        __syncthreads();
        // stage weights: Ws[kk][j] = Wg[j][k0+kk]  (global coalesced over kk)
        #pragma unroll 1
        for (int idx = tid; idx < NOUT*KC; idx += TPB){
            int j = idx >> 4, kk = idx & 15;
            if (kk < kc) Ws[kk*WSS + j] = Wg[j*wstride + k0 + kk];
        }
        __syncthreads();
        if (jq*4 < NOUT){
            const float* rowp = buf + (k0 - kbeg)*AS + mq*4;
            const float* wsp  = Ws + jq*4;
            #pragma unroll 1
            for (int kk = 0; kk < kc; kk++){
                float4 wv = *(const float4*)(wsp + kk*WSS);   // 4 weights, 1 LDS.128
                u64 w0 = pack2(wv.x), w1 = pack2(wv.y), w2v = pack2(wv.z), w3 = pack2(wv.w);
                ulonglong2 a0 = *(const ulonglong2*)(rowp);      // m: mq*4 + 0..3
                ulonglong2 a1 = *(const ulonglong2*)(rowp + 16); // m: 16 + mq*4 ..
                ulonglong2 a2 = *(const ulonglong2*)(rowp + 32);
                ulonglong2 a3 = *(const ulonglong2*)(rowp + 48);
                fma2(acc[ 0], a0.x, w0); fma2(acc[ 1], a0.y, w0);
                fma2(acc[ 2], a1.x, w0); fma2(acc[ 3], a1.y, w0);
                fma2(acc[ 4], a2.x, w0); fma2(acc[ 5], a2.y, w0);
                fma2(acc[ 6], a3.x, w0); fma2(acc[ 7], a3.y, w0);
                fma2(acc[ 8], a0.x, w1); fma2(acc[ 9], a0.y, w1);
                fma2(acc[10], a1.x, w1); fma2(acc[11], a1.y, w1);
                fma2(acc[12], a2.x, w1); fma2(acc[13], a2.y, w1);
                fma2(acc[14], a3.x, w1); fma2(acc[15], a3.y, w1);
                fma2(acc[16], a0.x, w2v); fma2(acc[17], a0.y, w2v);
                fma2(acc[18], a1.x, w2v); fma2(acc[19], a1.y, w2v);
                fma2(acc[20], a2.x, w2v); fma2(acc[21], a2.y, w2v);
                fma2(acc[22], a3.x, w2v); fma2(acc[23], a3.y, w2v);
                fma2(acc[24], a0.x, w3); fma2(acc[25], a0.y, w3);
                fma2(acc[26], a1.x, w3); fma2(acc[27], a1.y, w3);
                fma2(acc[28], a2.x, w3); fma2(acc[29], a2.y, w3);
                fma2(acc[30], a3.x, w3); fma2(acc[31], a3.y, w3);
                rowp += AS;
            }
        }
    }
}

template<int NOUT>
__device__ __forceinline__ void writeback_relu(u64 acc[32], const float* __restrict__ bg,
                                               float* dst0, int tid, int jq, int mq)
{
    __syncthreads();   // all reads of the input buffer done before overwrite
    if (jq*4 < NOUT){
        #pragma unroll
        for (int jj = 0; jj < 4; jj++){
            int j = jq*4 + jj;
            float b = bg[j];
            float* dst = dst0 + j*AS + mq*4;
            #pragma unroll
            for (int i = 0; i < 4; i++){
                #pragma unroll
                for (int p = 0; p < 2; p++){
                    float lo, hi; unpack2(acc[jj*8 + i*2 + p], lo, hi);
                    float2 v = make_float2(fmaxf(lo + b, 0.0f), fmaxf(hi + b, 0.0f));
                    *(float2*)(dst + i*16 + 2*p) = v;
                }
            }
        }
    }
}

__device__ __forceinline__ void zero_acc(u64 acc[32]){
    #pragma unroll
    for (int i = 0; i < 32; i++) acc[i] = 0ull;
}

__global__ void __launch_bounds__(TPB, 2) nerf_fused(NerfParams P)
{
    extern __shared__ float sm[];
    float* A  = sm;                 // [256][AS] activations (k-major)
    float* Pe = A  + 256*AS;        // [63][AS]  embedded pts
    float* De = Pe + 63*AS;         // [27][AS]  embedded dirs
    float* Ws = De + 27*AS;         // weight staging: [KC][WSS]
    const int tid = threadIdx.x;
    const int jq  = tid >> 2;       // 0..63  (4 outputs each)
    const int mq  = tid & 3;        // 0..3   (16 points each, interleaved by 4)
    const int g0  = blockIdx.x * MPT;
    const int N   = P.N;

    // ---- embeddings: [x, sin(2^f x)*3, cos(2^f x)*3, ...] f ascending ----
    for (int idx = tid; idx < MPT*3; idx += TPB){
        int m = idx/3, d = idx%3;
        Pe[d*AS+m] = P.pts [(g0+m)*3+d];
        De[d*AS+m] = P.dirs[(g0+m)*3+d];
    }
    for (int idx = tid; idx < MPT*30; idx += TPB){
        int m = idx/30, q = idx%30, f = q/3, d = q%3;
        float x = P.pts[(g0+m)*3+d] * (float)(1<<f);
        float s, c; sincosf(x, &s, &c);
        Pe[(3+f*6+d)*AS+m]   = s;
        Pe[(3+f*6+3+d)*AS+m] = c;
    }
    for (int idx = tid; idx < MPT*12; idx += TPB){
        int m = idx/12, q = idx%12, f = q/3, d = q%3;
        float x = P.dirs[(g0+m)*3+d] * (float)(1<<f);
        float s, c; sincosf(x, &s, &c);
        De[(3+f*6+d)*AS+m]   = s;
        De[(3+f*6+3+d)*AS+m] = c;
    }
    __syncthreads();

    // ---- third output: embedded dirs, out[4N + n*27 + k] ----
    {
        float* outD = P.out + 4ll*N;
        for (int idx = tid; idx < MPT*27; idx += TPB){
            int m = idx/27, k = idx%27;
            outD[(long long)(g0+m)*27 + k] = De[k*AS+m];
        }
    }

    u64 acc[32];

    // ---- layer 0: 63 -> 256 ----
    zero_acc(acc);
    gemm_pass<256>(acc, P.Wb[0], 63, 0, 63, Pe, Ws, tid, jq, mq);
    writeback_relu<256>(acc, P.bb[0], A, tid, jq, mq);

    // ---- layers 1..4: 256 -> 256 ----
    #pragma unroll 1
    for (int L = 1; L <= 4; L++){
        zero_acc(acc);
        gemm_pass<256>(acc, P.Wb[L], 256, 0, 256, A, Ws, tid, jq, mq);
        writeback_relu<256>(acc, P.bb[L], A, tid, jq, mq);
    }

    // ---- layer 5 with skip: [p(63), base(256)] -> 256 ----
    zero_acc(acc);
    gemm_pass<256>(acc, P.Wb[5], 319, 0, 63, Pe, Ws, tid, jq, mq);
    gemm_pass<256>(acc, P.Wb[5], 319, 63, 319, A, Ws, tid, jq, mq);
    writeback_relu<256>(acc, P.bb[5], A, tid, jq, mq);

    // ---- layers 6, 7: 256 -> 256 ----
    #pragma unroll 1
    for (int L = 6; L <= 7; L++){
        zero_acc(acc);
        gemm_pass<256>(acc, P.Wb[L], 256, 0, 256, A, Ws, tid, jq, mq);
        writeback_relu<256>(acc, P.bb[L], A, tid, jq, mq);
    }

    // ---- sigma = base @ Wsig.T + bsig (SIGMA_MUL=0) ----
    __syncthreads();
    Ws[tid] = P.Wsig[tid];          // stage the 256-vector
    __syncthreads();
    if (tid < MPT){
        float s = P.bsig[0];
        #pragma unroll 8
        for (int k = 0; k < 256; k++) s += A[k*AS+tid] * Ws[k];
        P.out[3ll*N + g0 + tid] = s;
    }
    // (next gemm_pass's first __syncthreads orders Ws reuse after these reads)

    // ---- base_remap = relu(base @ Wrm.T + brm) ----
    zero_acc(acc);
    gemm_pass<256>(acc, P.Wrm, 256, 0, 256, A, Ws, tid, jq, mq);
    writeback_relu<256>(acc, P.brm, A, tid, jq, mq);

    // ---- rgb_fea = relu([remap(256), d(27)] @ Wr0.T + br0), 128 outputs ----
    zero_acc(acc);
    gemm_pass<128>(acc, P.Wr0, 283, 0, 256, A, Ws, tid, jq, mq);
    gemm_pass<128>(acc, P.Wr0, 283, 256, 283, De, Ws, tid, jq, mq);
    writeback_relu<128>(acc, P.br0, A, tid, jq, mq);   // overwrites A rows 0..127
    __syncthreads();

    // ---- rgb = sigmoid(fea @ Wr1.T + br1) ----
    for (int idx = tid; idx < 384; idx += TPB) Ws[idx] = P.Wr1[idx];
    __syncthreads();
    if (tid < MPT){
        #pragma unroll
        for (int c = 0; c < 3; c++){
            float a = P.br1[c];
            #pragma unroll 8
            for (int k = 0; k < 128; k++) a += A[k*AS+tid] * Ws[c*128+k];
            P.out[(long long)(g0+tid)*3 + c] = 1.0f/(1.0f + expf(-a));
        }
    }
}

extern "C" void kernel_launch(void* const* d_in, const int* in_sizes, int n_in,
                              void* d_out, int out_size)
{
    NerfParams p;
    p.pts  = (const float*)d_in[0];
    p.dirs = (const float*)d_in[1];
    for (int i = 0; i < 8; i++){
        p.Wb[i] = (const float*)d_in[2 + 2*i];
        p.bb[i] = (const float*)d_in[3 + 2*i];
    }
    p.Wsig = (const float*)d_in[18]; p.bsig = (const float*)d_in[19];
    p.Wrm  = (const float*)d_in[20]; p.brm  = (const float*)d_in[21];
    p.Wr0  = (const float*)d_in[22]; p.br0  = (const float*)d_in[23];
    p.Wr1  = (const float*)d_in[24]; p.br1  = (const float*)d_in[25];
    p.out  = (float*)d_out;
    p.N    = in_sizes[0] / 3;

    size_t smem = (size_t)(256*AS + 63*AS + 27*AS + KC*WSS + 192) * sizeof(float);
    cudaFuncSetAttribute(nerf_fused, cudaFuncAttributeMaxDynamicSharedMemorySize, (int)smem);

    int blocks = p.N / MPT;   // 262144/64 = 4096
    nerf_fused<<<blocks, TPB, smem>>>(p);
}